// round 1
// baseline (speedup 1.0000x reference)
#include <cuda_runtime.h>
#include <math.h>

#define Rr   10000
#define E    256
#define Bb   1024
#define L    8
#define RP1  10001
#define SPLITK 5
#define KSPL  2000   // 10000 / 5, multiple of 16

// ---------------- scratch (static device arrays; no allocation) ----------------
__device__ float g_x[Bb*L*E];          // embedded inputs (B, L, E)
__device__ float g_hid[Bb*L*E];        // LSTM hidden outputs (B, L, E)
__device__ float g_h[Bb*E];
__device__ float g_c[Bb*E];
__device__ float g_act[Bb*2*E];        // [x_t, h] packed per step
__device__ float g_gates[Bb*4*E];
__device__ float g_hidden1[Bb*E];
__device__ float g_probsf[(size_t)Bb*RP1];
__device__ float g_wcat[4*E*2*E];      // [w_ih ; w_hh] packed (4E, 2E)
__device__ float g_biassum[4*E];
__device__ float g_part[SPLITK*Bb*E];  // split-K partials

// ---------------- small elementwise kernels ----------------
__global__ void prep_kernel(const float* __restrict__ w_ih, const float* __restrict__ w_hh,
                            const float* __restrict__ b_ih, const float* __restrict__ b_hh) {
    int idx = blockIdx.x*256 + threadIdx.x;          // 4E*2E = 524288
    int row = idx >> 9, j = idx & 511;
    g_wcat[idx] = (j < E) ? w_ih[row*E + j] : w_hh[row*E + (j-E)];
    if (idx < 4*E) g_biassum[idx] = b_ih[idx] + b_hh[idx];
}

__global__ void embed_kernel(const int* __restrict__ bodys, const float* __restrict__ emb_w) {
    int idx = blockIdx.x*256 + threadIdx.x;          // B*L*E = 2097152
    int bl = idx >> 8, e = idx & 255;
    g_x[idx] = emb_w[bodys[bl]*E + e];
    if (idx < Bb*E) { g_h[idx] = 0.f; g_c[idx] = 0.f; }
}

__global__ void pack_act_kernel(int t) {
    int idx = blockIdx.x*256 + threadIdx.x;          // B*512
    int b = idx >> 9, j = idx & 511;
    g_act[idx] = (j < E) ? g_x[b*(L*E) + t*E + j] : g_h[b*E + (j-E)];
}

__device__ __forceinline__ float sigm(float x) { return 1.f/(1.f + __expf(-x)); }

__global__ void lstm_cell_kernel(int t) {
    int idx = blockIdx.x*256 + threadIdx.x;          // B*E
    int b = idx >> 8, e = idx & 255;
    const float* g = g_gates + b*(4*E);
    float gi = g[e], gf = g[E+e], gg = g[2*E+e], go = g[3*E+e];
    float cc = sigm(gf)*g_c[idx] + sigm(gi)*tanhf(gg);
    float hh = sigm(go)*tanhf(cc);
    g_c[idx] = cc; g_h[idx] = hh;
    g_hid[b*(L*E) + t*E + e] = hh;
}

__global__ void concat0_kernel(float* __restrict__ out_emb) {
    int idx = blockIdx.x*256 + threadIdx.x;          // B*512
    int b = idx >> 9, j = idx & 511;
    // x[:,0,:] and x[:,1,:] are contiguous per batch row
    out_emb[idx] = g_x[b*(L*E) + j];
}

__global__ void emb1_finish_kernel(float* __restrict__ out_emb,
                                   const float* __restrict__ emb_w, int i) {
    int idx = blockIdx.x*256 + threadIdx.x;          // B*E
    int b = idx >> 8, e = idx & 255;
    float s = 0.f;
#pragma unroll
    for (int p = 0; p < SPLITK; p++) s += g_part[p*(Bb*E) + idx];
    s += g_probsf[(size_t)b*RP1 + Rr] * g_hid[b*(L*E) + i*E + e];
    out_emb[b*(2*E) + e]     = s;
    out_emb[b*(2*E) + E + e] = emb_w[(i+1)*E + e];
}

__global__ void softmax_kernel(const float* __restrict__ prob) {
    int b = blockIdx.x;
    const float* row = prob + (size_t)b*RP1;
    float* orow = g_probsf + (size_t)b*RP1;
    __shared__ float red[256];
    int t = threadIdx.x;
    float m = -1e30f;
    for (int j = t; j < RP1; j += 256) m = fmaxf(m, row[j]);
    red[t] = m; __syncthreads();
    for (int s = 128; s > 0; s >>= 1) { if (t < s) red[t] = fmaxf(red[t], red[t+s]); __syncthreads(); }
    m = red[0]; __syncthreads();
    float sum = 0.f;
    for (int j = t; j < RP1; j += 256) sum += __expf(row[j]-m);
    red[t] = sum; __syncthreads();
    for (int s = 128; s > 0; s >>= 1) { if (t < s) red[t] += red[t+s]; __syncthreads(); }
    float inv = 1.f/red[0];
    for (int j = t; j < RP1; j += 256) orow[j] = __expf(row[j]-m)*inv;
}

// ---------------- register-blocked fp32 GEMM ----------------
// TRANSB=1: C = A(M,K) @ B(N,K)^T ;  TRANSB=0: C = A(M,K) @ B(K,N)
// split-K via blockIdx.z: each z handles K window [z*Klen, (z+1)*Klen), writes C + z*M*ldc.
// M must be a multiple of 64; Klen a multiple of 16; N guarded.
#define BMT 64
#define BNT 64
#define BKT 16
template<bool TRANSB, bool RELU>
__global__ void gemm_kernel(const float* __restrict__ A, int lda,
                            const float* __restrict__ B, int ldb,
                            float* __restrict__ C, int ldc,
                            int M, int N, int Klen,
                            const float* __restrict__ bias)
{
    __shared__ float As[BKT][BMT+1];
    __shared__ float Bs[BKT][BNT+1];
    int bm = blockIdx.y*BMT, bn = blockIdx.x*BNT;
    int kbase = blockIdx.z*Klen;
    C += (size_t)blockIdx.z * M * ldc;
    int tid = threadIdx.x;
    int tx = tid & 15, ty = tid >> 4;
    float acc[4][4] = {};

    for (int kt = 0; kt < Klen; kt += BKT) {
#pragma unroll
        for (int j = 0; j < 4; j++) {
            int idx = tid + j*256;
            int m = idx >> 4, k = idx & 15;
            As[k][m] = A[(size_t)(bm+m)*lda + kbase + kt + k];
        }
#pragma unroll
        for (int j = 0; j < 4; j++) {
            int idx = tid + j*256;
            if (TRANSB) {
                int n = idx >> 4, k = idx & 15;
                Bs[k][n] = (bn+n < N) ? B[(size_t)(bn+n)*ldb + kbase + kt + k] : 0.f;
            } else {
                int k = idx >> 6, n = idx & 63;
                Bs[k][n] = (bn+n < N) ? B[(size_t)(kbase+kt+k)*ldb + bn + n] : 0.f;
            }
        }
        __syncthreads();
#pragma unroll
        for (int kk = 0; kk < BKT; kk++) {
            float a[4], bb[4];
#pragma unroll
            for (int i = 0; i < 4; i++) { a[i] = As[kk][ty*4+i]; bb[i] = Bs[kk][tx*4+i]; }
#pragma unroll
            for (int i = 0; i < 4; i++)
#pragma unroll
                for (int j = 0; j < 4; j++)
                    acc[i][j] += a[i]*bb[j];
        }
        __syncthreads();
    }

#pragma unroll
    for (int i = 0; i < 4; i++) {
        int m = bm + ty*4 + i;
#pragma unroll
        for (int j = 0; j < 4; j++) {
            int n = bn + tx*4 + j;
            if (n < N) {
                float v = acc[i][j];
                if (bias) v += bias[n];
                if (RELU) v = fmaxf(v, 0.f);
                C[(size_t)m*ldc + n] = v;
            }
        }
    }
}

// ---------------- launch ----------------
extern "C" void kernel_launch(void* const* d_in, const int* in_sizes, int n_in,
                              void* d_out, int out_size) {
    const int*   bodys = (const int*)  d_in[0];
    const float* emb_w = (const float*)d_in[1];
    const float* w_ih  = (const float*)d_in[2];
    const float* w_hh  = (const float*)d_in[3];
    const float* b_ih  = (const float*)d_in[4];
    const float* b_hh  = (const float*)d_in[5];
    const float* fc1_w = (const float*)d_in[6];
    const float* fc1_b = (const float*)d_in[7];
    const float* fc2_w = (const float*)d_in[8];
    const float* fc2_b = (const float*)d_in[9];

    float* out_prob = (float*)d_out;
    float* out_emb  = out_prob + (size_t)Bb*RP1;

    float *act, *gates, *hidden1, *probsf, *wcat, *biassum, *part;
    cudaGetSymbolAddress((void**)&act,     g_act);
    cudaGetSymbolAddress((void**)&gates,   g_gates);
    cudaGetSymbolAddress((void**)&hidden1, g_hidden1);
    cudaGetSymbolAddress((void**)&probsf,  g_probsf);
    cudaGetSymbolAddress((void**)&wcat,    g_wcat);
    cudaGetSymbolAddress((void**)&biassum, g_biassum);
    cudaGetSymbolAddress((void**)&part,    g_part);

    prep_kernel<<<2048, 256>>>(w_ih, w_hh, b_ih, b_hh);
    embed_kernel<<<8192, 256>>>(bodys, emb_w);

    // LSTM: gates = [x_t, h] @ [w_ih; w_hh]^T + (b_ih + b_hh)
    for (int t = 0; t < L; t++) {
        pack_act_kernel<<<2048, 256>>>(t);
        gemm_kernel<true, false><<<dim3(16, 16, 1), 256>>>(
            act, 2*E, wcat, 2*E, gates, 4*E, Bb, 4*E, 2*E, biassum);
        lstm_cell_kernel<<<1024, 256>>>(t);
    }

    for (int i = 0; i < L-1; i++) {
        if (i == 0) {
            concat0_kernel<<<2048, 256>>>(out_emb);
        } else {
            // emb_1 = prob_sf[:, :R] @ emb_w  (split-K x5, deterministic partials)
            gemm_kernel<false, false><<<dim3(4, 16, SPLITK), 256>>>(
                probsf, RP1, emb_w, E, part, E, Bb, E, KSPL, nullptr);
            emb1_finish_kernel<<<1024, 256>>>(out_emb, emb_w, i);
        }
        // hidden1 = relu(emb_concat @ fc1_w^T + fc1_b)
        gemm_kernel<true, true><<<dim3(4, 16, 1), 256>>>(
            out_emb, 2*E, fc1_w, 2*E, hidden1, E, Bb, E, 2*E, fc1_b);
        // prob = hidden1 @ fc2_w^T + fc2_b  -> straight into d_out
        gemm_kernel<true, false><<<dim3((RP1+BNT-1)/BNT, 16, 1), 256>>>(
            hidden1, E, fc2_w, E, out_prob, RP1, Bb, RP1, E, fc2_b);
        if (i < L-2) softmax_kernel<<<1024, 256>>>(out_prob);
    }
}

// round 2
// speedup vs baseline: 1.2188x; 1.2188x over previous
#include <cuda_runtime.h>
#include <math.h>

#define Rr   10000
#define E    256
#define Bb   1024
#define L    8
#define RP1  10001
#define RPAD 10016          // padded prob_sf row stride (mult of 16 floats)
#define SPLITK 10
#define KSPL  1000          // 10000/10, multiple of 8

// ---------------- scratch ----------------
__device__ float g_x[Bb*L*E];
__device__ float g_hid[Bb*L*E];
__device__ float g_h[Bb*E];
__device__ float g_c[Bb*E];
__device__ float g_act[Bb*2*E];
__device__ float g_gates[Bb*4*E];
__device__ float g_hidden1[Bb*E];
__device__ float g_probsf[(size_t)Bb*RPAD];
__device__ float g_wcat[4*E*2*E];
__device__ float g_biassum[4*E];
__device__ float g_part[SPLITK*Bb*E];

// ---------------- small elementwise kernels ----------------
__global__ void prep_kernel(const float* __restrict__ w_ih, const float* __restrict__ w_hh,
                            const float* __restrict__ b_ih, const float* __restrict__ b_hh) {
    int idx = blockIdx.x*256 + threadIdx.x;
    int row = idx >> 9, j = idx & 511;
    g_wcat[idx] = (j < E) ? w_ih[row*E + j] : w_hh[row*E + (j-E)];
    if (idx < 4*E) g_biassum[idx] = b_ih[idx] + b_hh[idx];
}

__global__ void embed_kernel(const int* __restrict__ bodys, const float* __restrict__ emb_w) {
    int idx = blockIdx.x*256 + threadIdx.x;
    int bl = idx >> 8, e = idx & 255;
    g_x[idx] = emb_w[bodys[bl]*E + e];
    if (idx < Bb*E) { g_h[idx] = 0.f; g_c[idx] = 0.f; }
}

__global__ void pack_act_kernel(int t) {
    int idx = blockIdx.x*256 + threadIdx.x;
    int b = idx >> 9, j = idx & 511;
    g_act[idx] = (j < E) ? g_x[b*(L*E) + t*E + j] : g_h[b*E + (j-E)];
}

__device__ __forceinline__ float sigm(float x) { return 1.f/(1.f + __expf(-x)); }

__global__ void lstm_cell_kernel(int t) {
    int idx = blockIdx.x*256 + threadIdx.x;
    int b = idx >> 8, e = idx & 255;
    const float* g = g_gates + b*(4*E);
    float gi = g[e], gf = g[E+e], gg = g[2*E+e], go = g[3*E+e];
    float cc = sigm(gf)*g_c[idx] + sigm(gi)*tanhf(gg);
    float hh = sigm(go)*tanhf(cc);
    g_c[idx] = cc; g_h[idx] = hh;
    g_hid[b*(L*E) + t*E + e] = hh;
}

__global__ void concat0_kernel(float* __restrict__ out_emb) {
    int idx = blockIdx.x*256 + threadIdx.x;
    int b = idx >> 9, j = idx & 511;
    out_emb[idx] = g_x[b*(L*E) + j];
}

__global__ void emb1_finish_kernel(float* __restrict__ out_emb,
                                   const float* __restrict__ emb_w, int i) {
    int idx = blockIdx.x*256 + threadIdx.x;
    int b = idx >> 8, e = idx & 255;
    float s = 0.f;
#pragma unroll
    for (int p = 0; p < SPLITK; p++) s += g_part[p*(Bb*E) + idx];
    s += g_probsf[(size_t)b*RPAD + Rr] * g_hid[b*(L*E) + i*E + e];
    out_emb[b*(2*E) + e]     = s;
    out_emb[b*(2*E) + E + e] = emb_w[(i+1)*E + e];
}

__global__ void softmax_kernel(const float* __restrict__ prob) {
    int b = blockIdx.x;
    const float* row = prob + (size_t)b*RP1;
    float* orow = g_probsf + (size_t)b*RPAD;
    __shared__ float red[256];
    int t = threadIdx.x;
    float m = -1e30f;
    for (int j = t; j < RP1; j += 256) m = fmaxf(m, row[j]);
    red[t] = m; __syncthreads();
    for (int s = 128; s > 0; s >>= 1) { if (t < s) red[t] = fmaxf(red[t], red[t+s]); __syncthreads(); }
    m = red[0]; __syncthreads();
    float sum = 0.f;
    for (int j = t; j < RP1; j += 256) sum += __expf(row[j]-m);
    red[t] = sum; __syncthreads();
    for (int s = 128; s > 0; s >>= 1) { if (t < s) red[t] += red[t+s]; __syncthreads(); }
    float inv = 1.f/red[0];
    for (int j = t; j < RP1; j += 256) orow[j] = __expf(row[j]-m)*inv;
    // pad tail (keeps GEMM K-reads defined; they stop at Rr anyway, but be safe)
    for (int j = RP1 + t; j < RPAD; j += 256) orow[j] = 0.f;
}

// ---------------- 128x128 double-buffered fp32 GEMM ----------------
// TRANSB=1: C = A(M,K) @ B(N,K)^T ; TRANSB=0: C = A(M,K) @ B(K,N)
// Requirements: M % 128 == 0; Klen % 8 == 0; lda/ldb/kbase multiples of 4 floats.
// split-K via blockIdx.z writing partials at C + z*M*ldc.
template<bool TRANSB, bool RELU>
__global__ void __launch_bounds__(256, 2)
gemm128(const float* __restrict__ A, int lda,
        const float* __restrict__ B, int ldb,
        float* __restrict__ C, int ldc,
        int M, int N, int Klen,
        const float* __restrict__ bias)
{
    __shared__ float As[2][8][128];
    __shared__ float Bs[2][8][128];

    const int bm = blockIdx.y*128, bn = blockIdx.x*128;
    const int kbase = blockIdx.z*Klen;
    C += (size_t)blockIdx.z * M * ldc;
    const int tid = threadIdx.x;
    const int tx = tid & 15, ty = tid >> 4;

    // A load: thread -> row = tid>>1, k4 = (tid&1)*4 (one float4)
    const int arow = tid >> 1, ak4 = (tid & 1) * 4;
    // B load (TRANSB): same pattern over n-rows. B load (NN): krow = tid>>5, n4=(tid&31)*4
    const int brow = tid >> 1, bk4 = (tid & 1) * 4;
    const int nkrow = tid >> 5, nn4 = (tid & 31) * 4;

    float acc[8][8];
#pragma unroll
    for (int i = 0; i < 8; i++)
#pragma unroll
        for (int j = 0; j < 8; j++) acc[i][j] = 0.f;

    const int ntiles = Klen >> 3;

    // helper lambdas via macros
    float4 ra, rb;
    // ---- load tile 0 ----
    {
        const int k0 = kbase;
        ra = *(const float4*)&A[(size_t)(bm+arow)*lda + k0 + ak4];
        if (TRANSB) {
            if (bn + brow < N) rb = *(const float4*)&B[(size_t)(bn+brow)*ldb + k0 + bk4];
            else rb = make_float4(0.f,0.f,0.f,0.f);
        } else {
            rb = *(const float4*)&B[(size_t)(k0+nkrow)*ldb + bn + nn4];
        }
        As[0][ak4+0][arow] = ra.x; As[0][ak4+1][arow] = ra.y;
        As[0][ak4+2][arow] = ra.z; As[0][ak4+3][arow] = ra.w;
        if (TRANSB) {
            Bs[0][bk4+0][brow] = rb.x; Bs[0][bk4+1][brow] = rb.y;
            Bs[0][bk4+2][brow] = rb.z; Bs[0][bk4+3][brow] = rb.w;
        } else {
            *(float4*)&Bs[0][nkrow][nn4] = rb;
        }
    }
    __syncthreads();

    for (int t = 0; t < ntiles; t++) {
        const int buf = t & 1;
        // prefetch tile t+1 into the other buffer (no sync needed before stores:
        // other buffer's reads completed at the sync ending iteration t-1)
        if (t + 1 < ntiles) {
            const int k0 = kbase + (t+1)*8;
            ra = *(const float4*)&A[(size_t)(bm+arow)*lda + k0 + ak4];
            if (TRANSB) {
                if (bn + brow < N) rb = *(const float4*)&B[(size_t)(bn+brow)*ldb + k0 + bk4];
                else rb = make_float4(0.f,0.f,0.f,0.f);
            } else {
                rb = *(const float4*)&B[(size_t)(k0+nkrow)*ldb + bn + nn4];
            }
            const int nb = buf ^ 1;
            As[nb][ak4+0][arow] = ra.x; As[nb][ak4+1][arow] = ra.y;
            As[nb][ak4+2][arow] = ra.z; As[nb][ak4+3][arow] = ra.w;
            if (TRANSB) {
                Bs[nb][bk4+0][brow] = rb.x; Bs[nb][bk4+1][brow] = rb.y;
                Bs[nb][bk4+2][brow] = rb.z; Bs[nb][bk4+3][brow] = rb.w;
            } else {
                *(float4*)&Bs[nb][nkrow][nn4] = rb;
            }
        }
#pragma unroll
        for (int kk = 0; kk < 8; kk++) {
            const float4* Ar = (const float4*)As[buf][kk];
            const float4* Br = (const float4*)Bs[buf][kk];
            float4 a0 = Ar[ty], a1 = Ar[16+ty];
            float4 b0 = Br[tx], b1 = Br[16+tx];
            float av[8] = {a0.x,a0.y,a0.z,a0.w,a1.x,a1.y,a1.z,a1.w};
            float bv[8] = {b0.x,b0.y,b0.z,b0.w,b1.x,b1.y,b1.z,b1.w};
#pragma unroll
            for (int i = 0; i < 8; i++)
#pragma unroll
                for (int j = 0; j < 8; j++)
                    acc[i][j] += av[i]*bv[j];
        }
        __syncthreads();
    }

    // epilogue
#pragma unroll
    for (int i = 0; i < 8; i++) {
        int m = bm + ((i < 4) ? (ty*4 + i) : (64 + ty*4 + i - 4));
#pragma unroll
        for (int j = 0; j < 8; j++) {
            int n = bn + ((j < 4) ? (tx*4 + j) : (64 + tx*4 + j - 4));
            if (n < N) {
                float v = acc[i][j];
                if (bias) v += bias[n];
                if (RELU) v = fmaxf(v, 0.f);
                C[(size_t)m*ldc + n] = v;
            }
        }
    }
}

// ---------------- 64x64 GEMM (kept for fc1) ----------------
#define BMT 64
#define BNT 64
#define BKT 16
template<bool TRANSB, bool RELU>
__global__ void gemm_kernel(const float* __restrict__ A, int lda,
                            const float* __restrict__ B, int ldb,
                            float* __restrict__ C, int ldc,
                            int M, int N, int Klen,
                            const float* __restrict__ bias)
{
    __shared__ float As[BKT][BMT+1];
    __shared__ float Bs[BKT][BNT+1];
    int bm = blockIdx.y*BMT, bn = blockIdx.x*BNT;
    int kbase = blockIdx.z*Klen;
    C += (size_t)blockIdx.z * M * ldc;
    int tid = threadIdx.x;
    int tx = tid & 15, ty = tid >> 4;
    float acc[4][4] = {};

    for (int kt = 0; kt < Klen; kt += BKT) {
#pragma unroll
        for (int j = 0; j < 4; j++) {
            int idx = tid + j*256;
            int m = idx >> 4, k = idx & 15;
            As[k][m] = A[(size_t)(bm+m)*lda + kbase + kt + k];
        }
#pragma unroll
        for (int j = 0; j < 4; j++) {
            int idx = tid + j*256;
            if (TRANSB) {
                int n = idx >> 4, k = idx & 15;
                Bs[k][n] = (bn+n < N) ? B[(size_t)(bn+n)*ldb + kbase + kt + k] : 0.f;
            } else {
                int k = idx >> 6, n = idx & 63;
                Bs[k][n] = (bn+n < N) ? B[(size_t)(kbase+kt+k)*ldb + bn + n] : 0.f;
            }
        }
        __syncthreads();
#pragma unroll
        for (int kk = 0; kk < BKT; kk++) {
            float a[4], bb[4];
#pragma unroll
            for (int i = 0; i < 4; i++) { a[i] = As[kk][ty*4+i]; bb[i] = Bs[kk][tx*4+i]; }
#pragma unroll
            for (int i = 0; i < 4; i++)
#pragma unroll
                for (int j = 0; j < 4; j++)
                    acc[i][j] += a[i]*bb[j];
        }
        __syncthreads();
    }

#pragma unroll
    for (int i = 0; i < 4; i++) {
        int m = bm + ty*4 + i;
#pragma unroll
        for (int j = 0; j < 4; j++) {
            int n = bn + tx*4 + j;
            if (n < N) {
                float v = acc[i][j];
                if (bias) v += bias[n];
                if (RELU) v = fmaxf(v, 0.f);
                C[(size_t)m*ldc + n] = v;
            }
        }
    }
}

// ---------------- launch ----------------
extern "C" void kernel_launch(void* const* d_in, const int* in_sizes, int n_in,
                              void* d_out, int out_size) {
    const int*   bodys = (const int*)  d_in[0];
    const float* emb_w = (const float*)d_in[1];
    const float* w_ih  = (const float*)d_in[2];
    const float* w_hh  = (const float*)d_in[3];
    const float* b_ih  = (const float*)d_in[4];
    const float* b_hh  = (const float*)d_in[5];
    const float* fc1_w = (const float*)d_in[6];
    const float* fc1_b = (const float*)d_in[7];
    const float* fc2_w = (const float*)d_in[8];
    const float* fc2_b = (const float*)d_in[9];

    float* out_prob = (float*)d_out;
    float* out_emb  = out_prob + (size_t)Bb*RP1;

    float *act, *gates, *hidden1, *probsf, *wcat, *biassum, *part;
    cudaGetSymbolAddress((void**)&act,     g_act);
    cudaGetSymbolAddress((void**)&gates,   g_gates);
    cudaGetSymbolAddress((void**)&hidden1, g_hidden1);
    cudaGetSymbolAddress((void**)&probsf,  g_probsf);
    cudaGetSymbolAddress((void**)&wcat,    g_wcat);
    cudaGetSymbolAddress((void**)&biassum, g_biassum);
    cudaGetSymbolAddress((void**)&part,    g_part);

    prep_kernel<<<2048, 256>>>(w_ih, w_hh, b_ih, b_hh);
    embed_kernel<<<8192, 256>>>(bodys, emb_w);

    // LSTM: gates = [x_t, h] @ [w_ih; w_hh]^T + (b_ih + b_hh)
    for (int t = 0; t < L; t++) {
        pack_act_kernel<<<2048, 256>>>(t);
        gemm128<true, false><<<dim3(8, 8, 1), 256>>>(
            act, 2*E, wcat, 2*E, gates, 4*E, Bb, 4*E, 2*E, biassum);
        lstm_cell_kernel<<<1024, 256>>>(t);
    }

    for (int i = 0; i < L-1; i++) {
        if (i == 0) {
            concat0_kernel<<<2048, 256>>>(out_emb);
        } else {
            // emb_1 = prob_sf[:, :R] @ emb_w  (split-K x10, deterministic partials)
            gemm128<false, false><<<dim3(2, 8, SPLITK), 256>>>(
                probsf, RPAD, emb_w, E, part, E, Bb, E, KSPL, nullptr);
            emb1_finish_kernel<<<1024, 256>>>(out_emb, emb_w, i);
        }
        // hidden1 = relu(emb_concat @ fc1_w^T + fc1_b)
        gemm_kernel<true, true><<<dim3(4, 16, 1), 256>>>(
            out_emb, 2*E, fc1_w, 2*E, hidden1, E, Bb, E, 2*E, fc1_b);
        // prob = hidden1 @ fc2_w^T + fc2_b
        gemm128<true, false><<<dim3((RP1+127)/128, 8, 1), 256>>>(
            hidden1, E, fc2_w, E, out_prob, RP1, Bb, RP1, E, fc2_b);
        if (i < L-2) softmax_kernel<<<1024, 256>>>(out_prob);
    }
}

// round 3
// speedup vs baseline: 1.3474x; 1.1055x over previous
#include <cuda_runtime.h>
#include <math.h>

#define Rr   10000
#define E    256
#define Bb   1024
#define L    8
#define RP1  10001
#define RPAD 10016
#define SPLITK 10
#define KSPL  1000

// packed f32x2 helpers (Blackwell FFMA2 path)
#define PACKF2(d, lo, hi) asm("mov.b64 %0, {%1, %2};" : "=l"(d) : "f"(lo), "f"(hi))
#define FMAF2(acc, a, b)  asm("fma.rn.f32x2 %0, %1, %2, %0;" : "+l"(acc) : "l"(a), "l"(b))
#define UNPACKF2(lo, hi, v) asm("mov.b64 {%0, %1}, %2;" : "=f"(lo), "=f"(hi) : "l"(v))

// ---------------- scratch ----------------
__device__ float g_x[Bb*L*E];
__device__ float g_hid[Bb*L*E];
__device__ float g_h[Bb*E];
__device__ float g_c[Bb*E];
__device__ float g_act[Bb*2*E];
__device__ float g_gates[Bb*4*E];
__device__ float g_hidden1[Bb*E];
__device__ float g_probsf[(size_t)Bb*RPAD];
__device__ float g_wcat[4*E*2*E];
__device__ float g_biassum[4*E];
__device__ float g_part[SPLITK*Bb*E];

// ---------------- small elementwise kernels ----------------
__global__ void prep_kernel(const float* __restrict__ w_ih, const float* __restrict__ w_hh,
                            const float* __restrict__ b_ih, const float* __restrict__ b_hh) {
    int idx = blockIdx.x*256 + threadIdx.x;
    int row = idx >> 9, j = idx & 511;
    g_wcat[idx] = (j < E) ? w_ih[row*E + j] : w_hh[row*E + (j-E)];
    if (idx < 4*E) g_biassum[idx] = b_ih[idx] + b_hh[idx];
}

__global__ void embed_kernel(const int* __restrict__ bodys, const float* __restrict__ emb_w) {
    int idx = blockIdx.x*256 + threadIdx.x;
    int bl = idx >> 8, e = idx & 255;
    g_x[idx] = emb_w[bodys[bl]*E + e];
    if (idx < Bb*E) { g_h[idx] = 0.f; g_c[idx] = 0.f; }
}

__global__ void pack_act_kernel(int t) {
    int idx = blockIdx.x*256 + threadIdx.x;
    int b = idx >> 9, j = idx & 511;
    g_act[idx] = (j < E) ? g_x[b*(L*E) + t*E + j] : g_h[b*E + (j-E)];
}

__device__ __forceinline__ float sigm(float x) { return 1.f/(1.f + __expf(-x)); }

__global__ void lstm_cell_kernel(int t) {
    int idx = blockIdx.x*256 + threadIdx.x;
    int b = idx >> 8, e = idx & 255;
    const float* g = g_gates + b*(4*E);
    float gi = g[e], gf = g[E+e], gg = g[2*E+e], go = g[3*E+e];
    float cc = sigm(gf)*g_c[idx] + sigm(gi)*tanhf(gg);
    float hh = sigm(go)*tanhf(cc);
    g_c[idx] = cc; g_h[idx] = hh;
    g_hid[b*(L*E) + t*E + e] = hh;
}

__global__ void concat0_kernel(float* __restrict__ out_emb) {
    int idx = blockIdx.x*256 + threadIdx.x;
    int b = idx >> 9, j = idx & 511;
    out_emb[idx] = g_x[b*(L*E) + j];
}

__global__ void emb1_finish_kernel(float* __restrict__ out_emb,
                                   const float* __restrict__ emb_w, int i) {
    int idx = blockIdx.x*256 + threadIdx.x;
    int b = idx >> 8, e = idx & 255;
    float s = 0.f;
#pragma unroll
    for (int p = 0; p < SPLITK; p++) s += g_part[p*(Bb*E) + idx];
    s += g_probsf[(size_t)b*RPAD + Rr] * g_hid[b*(L*E) + i*E + e];
    out_emb[b*(2*E) + e]     = s;
    out_emb[b*(2*E) + E + e] = emb_w[(i+1)*E + e];
}

__global__ void softmax_kernel(const float* __restrict__ prob) {
    int b = blockIdx.x;
    const float* row = prob + (size_t)b*RP1;
    float* orow = g_probsf + (size_t)b*RPAD;
    __shared__ float red[256];
    int t = threadIdx.x;
    float m = -1e30f;
    for (int j = t; j < RP1; j += 256) m = fmaxf(m, row[j]);
    red[t] = m; __syncthreads();
    for (int s = 128; s > 0; s >>= 1) { if (t < s) red[t] = fmaxf(red[t], red[t+s]); __syncthreads(); }
    m = red[0]; __syncthreads();
    float sum = 0.f;
    for (int j = t; j < RP1; j += 256) sum += __expf(row[j]-m);
    red[t] = sum; __syncthreads();
    for (int s = 128; s > 0; s >>= 1) { if (t < s) red[t] += red[t+s]; __syncthreads(); }
    float inv = 1.f/red[0];
    for (int j = t; j < RP1; j += 256) orow[j] = __expf(row[j]-m)*inv;
    for (int j = RP1 + t; j < RPAD; j += 256) orow[j] = 0.f;
}

// ---------------- 128x128 double-buffered fp32 GEMM, FFMA2 inner loop ----------------
// TRANSB=1: C = A(M,K) @ B(N,K)^T ; TRANSB=0: C = A(M,K) @ B(K,N)
// M % 128 == 0; Klen % 8 == 0; pointers/strides 16B aligned.
template<bool TRANSB, bool RELU>
__global__ void __launch_bounds__(256, 2)
gemm128(const float* __restrict__ A, int lda,
        const float* __restrict__ B, int ldb,
        float* __restrict__ C, int ldc,
        int M, int N, int Klen,
        const float* __restrict__ bias)
{
    __shared__ float As[2][8][128];
    __shared__ float Bs[2][8][128];

    const int bm = blockIdx.y*128, bn = blockIdx.x*128;
    const int kbase = blockIdx.z*Klen;
    C += (size_t)blockIdx.z * M * ldc;
    const int tid = threadIdx.x;
    const int tx = tid & 15, ty = tid >> 4;

    const int arow = tid >> 1, ak4 = (tid & 1) * 4;
    const int brow = tid >> 1, bk4 = (tid & 1) * 4;
    const int nkrow = tid >> 5, nn4 = (tid & 31) * 4;

    unsigned long long acc[8][4];
#pragma unroll
    for (int i = 0; i < 8; i++)
#pragma unroll
        for (int j = 0; j < 4; j++) acc[i][j] = 0ULL;

    const int ntiles = Klen >> 3;
    float4 ra, rb;
    {
        const int k0 = kbase;
        ra = *(const float4*)&A[(size_t)(bm+arow)*lda + k0 + ak4];
        if (TRANSB) {
            if (bn + brow < N) rb = *(const float4*)&B[(size_t)(bn+brow)*ldb + k0 + bk4];
            else rb = make_float4(0.f,0.f,0.f,0.f);
        } else {
            rb = *(const float4*)&B[(size_t)(k0+nkrow)*ldb + bn + nn4];
        }
        As[0][ak4+0][arow] = ra.x; As[0][ak4+1][arow] = ra.y;
        As[0][ak4+2][arow] = ra.z; As[0][ak4+3][arow] = ra.w;
        if (TRANSB) {
            Bs[0][bk4+0][brow] = rb.x; Bs[0][bk4+1][brow] = rb.y;
            Bs[0][bk4+2][brow] = rb.z; Bs[0][bk4+3][brow] = rb.w;
        } else {
            *(float4*)&Bs[0][nkrow][nn4] = rb;
        }
    }
    __syncthreads();

    for (int t = 0; t < ntiles; t++) {
        const int buf = t & 1;
        if (t + 1 < ntiles) {
            const int k0 = kbase + (t+1)*8;
            ra = *(const float4*)&A[(size_t)(bm+arow)*lda + k0 + ak4];
            if (TRANSB) {
                if (bn + brow < N) rb = *(const float4*)&B[(size_t)(bn+brow)*ldb + k0 + bk4];
                else rb = make_float4(0.f,0.f,0.f,0.f);
            } else {
                rb = *(const float4*)&B[(size_t)(k0+nkrow)*ldb + bn + nn4];
            }
            const int nb = buf ^ 1;
            As[nb][ak4+0][arow] = ra.x; As[nb][ak4+1][arow] = ra.y;
            As[nb][ak4+2][arow] = ra.z; As[nb][ak4+3][arow] = ra.w;
            if (TRANSB) {
                Bs[nb][bk4+0][brow] = rb.x; Bs[nb][bk4+1][brow] = rb.y;
                Bs[nb][bk4+2][brow] = rb.z; Bs[nb][bk4+3][brow] = rb.w;
            } else {
                *(float4*)&Bs[nb][nkrow][nn4] = rb;
            }
        }
#pragma unroll
        for (int kk = 0; kk < 8; kk++) {
            const float4* Ar = (const float4*)As[buf][kk];
            const float4* Br = (const float4*)Bs[buf][kk];
            float4 a0 = Ar[ty], a1 = Ar[16+ty];
            float4 b0 = Br[tx], b1 = Br[16+tx];
            unsigned long long bp[4];
            PACKF2(bp[0], b0.x, b0.y); PACKF2(bp[1], b0.z, b0.w);
            PACKF2(bp[2], b1.x, b1.y); PACKF2(bp[3], b1.z, b1.w);
            float av[8] = {a0.x,a0.y,a0.z,a0.w,a1.x,a1.y,a1.z,a1.w};
#pragma unroll
            for (int i = 0; i < 8; i++) {
                unsigned long long a2;
                PACKF2(a2, av[i], av[i]);
#pragma unroll
                for (int j = 0; j < 4; j++) FMAF2(acc[i][j], a2, bp[j]);
            }
        }
        __syncthreads();
    }

#pragma unroll
    for (int i = 0; i < 8; i++) {
        int m = bm + ((i < 4) ? (ty*4 + i) : (64 + ty*4 + i - 4));
#pragma unroll
        for (int j = 0; j < 4; j++) {
            int nbase = bn + ((j < 2) ? (tx*4 + 2*j) : (64 + tx*4 + 2*(j-2)));
            float lo, hi;
            UNPACKF2(lo, hi, acc[i][j]);
            if (nbase < N) {
                float v = lo;
                if (bias) v += bias[nbase];
                if (RELU) v = fmaxf(v, 0.f);
                C[(size_t)m*ldc + nbase] = v;
            }
            if (nbase + 1 < N) {
                float v = hi;
                if (bias) v += bias[nbase+1];
                if (RELU) v = fmaxf(v, 0.f);
                C[(size_t)m*ldc + nbase + 1] = v;
            }
        }
    }
}

// ---------------- 64x64 GEMM (LSTM gates, fc1), FFMA2 inner loop ----------------
#define BMT 64
#define BNT 64
#define BKT 16
template<bool TRANSB, bool RELU>
__global__ void gemm_kernel(const float* __restrict__ A, int lda,
                            const float* __restrict__ B, int ldb,
                            float* __restrict__ C, int ldc,
                            int M, int N, int Klen,
                            const float* __restrict__ bias)
{
    __shared__ float As[BKT][BMT+4];
    __shared__ float Bs[BKT][BNT+4];
    int bm = blockIdx.y*BMT, bn = blockIdx.x*BNT;
    int kbase = blockIdx.z*Klen;
    C += (size_t)blockIdx.z * M * ldc;
    int tid = threadIdx.x;
    int tx = tid & 15, ty = tid >> 4;
    unsigned long long acc[4][2];
#pragma unroll
    for (int i = 0; i < 4; i++) { acc[i][0] = 0ULL; acc[i][1] = 0ULL; }

    for (int kt = 0; kt < Klen; kt += BKT) {
#pragma unroll
        for (int j = 0; j < 4; j++) {
            int idx = tid + j*256;
            int m = idx >> 4, k = idx & 15;
            As[k][m] = A[(size_t)(bm+m)*lda + kbase + kt + k];
        }
#pragma unroll
        for (int j = 0; j < 4; j++) {
            int idx = tid + j*256;
            if (TRANSB) {
                int n = idx >> 4, k = idx & 15;
                Bs[k][n] = (bn+n < N) ? B[(size_t)(bn+n)*ldb + kbase + kt + k] : 0.f;
            } else {
                int k = idx >> 6, n = idx & 63;
                Bs[k][n] = (bn+n < N) ? B[(size_t)(kbase+kt+k)*ldb + bn + n] : 0.f;
            }
        }
        __syncthreads();
#pragma unroll
        for (int kk = 0; kk < BKT; kk++) {
            float4 a4 = *(const float4*)&As[kk][ty*4];
            float4 b4 = *(const float4*)&Bs[kk][tx*4];
            unsigned long long bp0, bp1;
            PACKF2(bp0, b4.x, b4.y); PACKF2(bp1, b4.z, b4.w);
            float av[4] = {a4.x, a4.y, a4.z, a4.w};
#pragma unroll
            for (int i = 0; i < 4; i++) {
                unsigned long long a2;
                PACKF2(a2, av[i], av[i]);
                FMAF2(acc[i][0], a2, bp0);
                FMAF2(acc[i][1], a2, bp1);
            }
        }
        __syncthreads();
    }

#pragma unroll
    for (int i = 0; i < 4; i++) {
        int m = bm + ty*4 + i;
#pragma unroll
        for (int j = 0; j < 2; j++) {
            int nbase = bn + tx*4 + 2*j;
            float lo, hi;
            UNPACKF2(lo, hi, acc[i][j]);
            if (nbase < N) {
                float v = lo;
                if (bias) v += bias[nbase];
                if (RELU) v = fmaxf(v, 0.f);
                C[(size_t)m*ldc + nbase] = v;
            }
            if (nbase + 1 < N) {
                float v = hi;
                if (bias) v += bias[nbase+1];
                if (RELU) v = fmaxf(v, 0.f);
                C[(size_t)m*ldc + nbase + 1] = v;
            }
        }
    }
}

// ---------------- launch ----------------
extern "C" void kernel_launch(void* const* d_in, const int* in_sizes, int n_in,
                              void* d_out, int out_size) {
    const int*   bodys = (const int*)  d_in[0];
    const float* emb_w = (const float*)d_in[1];
    const float* w_ih  = (const float*)d_in[2];
    const float* w_hh  = (const float*)d_in[3];
    const float* b_ih  = (const float*)d_in[4];
    const float* b_hh  = (const float*)d_in[5];
    const float* fc1_w = (const float*)d_in[6];
    const float* fc1_b = (const float*)d_in[7];
    const float* fc2_w = (const float*)d_in[8];
    const float* fc2_b = (const float*)d_in[9];

    float* out_prob = (float*)d_out;
    float* out_emb  = out_prob + (size_t)Bb*RP1;

    float *act, *gates, *hidden1, *probsf, *wcat, *biassum, *part;
    cudaGetSymbolAddress((void**)&act,     g_act);
    cudaGetSymbolAddress((void**)&gates,   g_gates);
    cudaGetSymbolAddress((void**)&hidden1, g_hidden1);
    cudaGetSymbolAddress((void**)&probsf,  g_probsf);
    cudaGetSymbolAddress((void**)&wcat,    g_wcat);
    cudaGetSymbolAddress((void**)&biassum, g_biassum);
    cudaGetSymbolAddress((void**)&part,    g_part);

    prep_kernel<<<2048, 256>>>(w_ih, w_hh, b_ih, b_hh);
    embed_kernel<<<8192, 256>>>(bodys, emb_w);

    // LSTM: gates = [x_t, h] @ [w_ih; w_hh]^T + (b_ih + b_hh)  (256 blocks -> full chip)
    for (int t = 0; t < L; t++) {
        pack_act_kernel<<<2048, 256>>>(t);
        gemm_kernel<true, false><<<dim3(16, 16, 1), 256>>>(
            act, 2*E, wcat, 2*E, gates, 4*E, Bb, 4*E, 2*E, biassum);
        lstm_cell_kernel<<<1024, 256>>>(t);
    }

    for (int i = 0; i < L-1; i++) {
        if (i == 0) {
            concat0_kernel<<<2048, 256>>>(out_emb);
        } else {
            gemm128<false, false><<<dim3(2, 8, SPLITK), 256>>>(
                probsf, RPAD, emb_w, E, part, E, Bb, E, KSPL, nullptr);
            emb1_finish_kernel<<<1024, 256>>>(out_emb, emb_w, i);
        }
        gemm_kernel<true, true><<<dim3(4, 16, 1), 256>>>(
            out_emb, 2*E, fc1_w, 2*E, hidden1, E, Bb, E, 2*E, fc1_b);
        gemm128<true, false><<<dim3((RP1+127)/128, 8, 1), 256>>>(
            hidden1, E, fc2_w, E, out_prob, RP1, Bb, RP1, E, fc2_b);
        if (i < L-2) softmax_kernel<<<1024, 256>>>(out_prob);
    }
}

// round 5
// speedup vs baseline: 2.4705x; 1.8335x over previous
#include <cuda_runtime.h>
#include <cuda_bf16.h>
#include <math.h>
#include <stdint.h>

#define Rr   10000
#define E    256
#define Bb   1024
#define L    8
#define RP1  10001
#define KPAD 10240            // padded K for probsf@emb_w (mult of 32)
#define NPADW 10112           // fc2_w rows padded to 79*128
#define SPLITK 10
#define KSPL 1024             // KPAD / SPLITK, mult of 32

// packed f32x2 helpers (Blackwell FFMA2)
#define PACKF2(d, lo, hi) asm("mov.b64 %0, {%1, %2};" : "=l"(d) : "f"(lo), "f"(hi))
#define FMAF2(acc, a, b)  asm("fma.rn.f32x2 %0, %1, %2, %0;" : "+l"(acc) : "l"(a), "l"(b))
#define UNPACKF2(lo, hi, v) asm("mov.b64 {%0, %1}, %2;" : "=f"(lo), "=f"(hi) : "l"(v))

// ---------------- scratch ----------------
__device__ float g_xT[Bb*L*E];                    // [t*1024+b][E]
__device__ float g_hid[Bb*L*E];                   // [b][t][E]
__device__ float g_h[Bb*E];
__device__ float g_c[Bb*E];
__device__ float g_gates[Bb*4*E];
__device__ float g_gx[(size_t)Bb*L*4*E];          // [t*1024+b][4E]
__device__ float g_hidden1[Bb*E];
__device__ __nv_bfloat16 g_h1hi[Bb*E];
__device__ __nv_bfloat16 g_h1lo[Bb*E];
__device__ __nv_bfloat16 g_psfhi[(size_t)Bb*KPAD];
__device__ __nv_bfloat16 g_psflo[(size_t)Bb*KPAD];
__device__ float g_psflast[Bb];
__device__ __nv_bfloat16 g_embThi[(size_t)E*KPAD]; // [e][k] K-major
__device__ __nv_bfloat16 g_embTlo[(size_t)E*KPAD];
__device__ __nv_bfloat16 g_fc2whi[(size_t)NPADW*E];
__device__ __nv_bfloat16 g_fc2wlo[(size_t)NPADW*E];
__device__ float g_biassum[4*E];
__device__ float g_part[SPLITK*Bb*E];

// ---------------- ptx helpers ----------------
__device__ __forceinline__ uint32_t s2u(const void* p) {
    uint32_t a;
    asm("{ .reg .u64 t; cvta.to.shared.u64 t, %1; cvt.u32.u64 %0, t; }" : "=r"(a) : "l"(p));
    return a;
}
__device__ __forceinline__ void ldm4(uint32_t* r, uint32_t addr) {
    asm volatile("ldmatrix.sync.aligned.m8n8.x4.shared.b16 {%0,%1,%2,%3}, [%4];"
                 : "=r"(r[0]), "=r"(r[1]), "=r"(r[2]), "=r"(r[3]) : "r"(addr));
}
__device__ __forceinline__ void mma_bf16(float* d, const uint32_t* a, const uint32_t* b) {
    asm volatile("mma.sync.aligned.m16n8k16.row.col.f32.bf16.bf16.f32 "
                 "{%0,%1,%2,%3}, {%4,%5,%6,%7}, {%8,%9}, {%0,%1,%2,%3};"
                 : "+f"(d[0]), "+f"(d[1]), "+f"(d[2]), "+f"(d[3])
                 : "r"(a[0]), "r"(a[1]), "r"(a[2]), "r"(a[3]), "r"(b[0]), "r"(b[1]));
}

// ---------------- warp-MMA split-bf16 GEMM ----------------
// C(128x128 tile) = (Ahi+Alo) @ (Bhi+Blo)^T  via 3 passes, fp32 accum.
// A: [M][K] K-major bf16, B: [N][K] K-major bf16. Klen % 32 == 0.
// blockIdx.z picks K window (kbase = z*Klen) and output slice (C += z*zstride).
#define SSTR 40   // smem row stride in bf16 elems (32 data + 8 pad) -> conflict-free ldmatrix
__global__ void __launch_bounds__(256)
hmma_gemm(const __nv_bfloat16* __restrict__ Ahi, const __nv_bfloat16* __restrict__ Alo, int lda,
          const __nv_bfloat16* __restrict__ Bhi, const __nv_bfloat16* __restrict__ Blo, int ldb,
          float* __restrict__ C, int ldc, int Nreal, int Klen, size_t zstride,
          const float* __restrict__ bias)
{
    __shared__ __nv_bfloat16 sAhi[128*SSTR], sAlo[128*SSTR];
    __shared__ __nv_bfloat16 sBhi[128*SSTR], sBlo[128*SSTR];

    const int tid = threadIdx.x, lane = tid & 31, wid = tid >> 5;
    const int bm = blockIdx.y * 128, bn = blockIdx.x * 128;
    const int kbase = blockIdx.z * Klen;
    C += (size_t)blockIdx.z * zstride;
    const int wm = (wid & 1) * 64, wn = (wid >> 1) * 32;

    float acc[4][4][4];
#pragma unroll
    for (int i = 0; i < 4; i++)
#pragma unroll
        for (int j = 0; j < 4; j++)
#pragma unroll
            for (int u = 0; u < 4; u++) acc[i][j][u] = 0.f;

    const uint32_t aHi = s2u(sAhi), aLo = s2u(sAlo);
    const uint32_t bHi = s2u(sBhi), bLo = s2u(sBlo);

    // ldmatrix lane addressing (bytes)
    const int l15 = lane & 15, lq = lane >> 4;       // A: row l15, col-half lq
    const int l8 = lane & 7, sel = lane >> 3;        // B: see below
    // A frag smem offsets per mf, ks (elements): (wm+mf*16+l15)*SSTR + ks*16 + lq*8
    // B frag: per pair p: row = wn + p*16 + (sel>>1)*8 + l8 ; col = ks*16 + (sel&1)*8

    for (int kt = 0; kt < Klen; kt += 32) {
        // global -> smem: 4 buffers, each 128 rows x 32 bf16 (4 uint4/row)
#pragma unroll
        for (int i = 0; i < 2; i++) {
            int idx = tid + i * 256;
            int row = idx >> 2, q = idx & 3;
            size_t ga = (size_t)(bm + row) * lda + kbase + kt + q * 8;
            size_t gb = (size_t)(bn + row) * ldb + kbase + kt + q * 8;
            int so = row * SSTR + q * 8;
            *(uint4*)&sAhi[so] = *(const uint4*)(Ahi + ga);
            *(uint4*)&sAlo[so] = *(const uint4*)(Alo + ga);
            *(uint4*)&sBhi[so] = *(const uint4*)(Bhi + gb);
            *(uint4*)&sBlo[so] = *(const uint4*)(Blo + gb);
        }
        __syncthreads();

#pragma unroll
        for (int ks = 0; ks < 2; ks++) {
            uint32_t ahi[4][4], alo[4][4];
#pragma unroll
            for (int mf = 0; mf < 4; mf++) {
                uint32_t off = (uint32_t)((wm + mf * 16 + l15) * SSTR + ks * 16 + lq * 8) * 2;
                ldm4(ahi[mf], aHi + off);
                ldm4(alo[mf], aLo + off);
            }
            uint32_t bhi[4][2], blo[4][2];
#pragma unroll
            for (int p = 0; p < 2; p++) {
                uint32_t off = (uint32_t)((wn + p * 16 + (sel >> 1) * 8 + l8) * SSTR
                                          + ks * 16 + (sel & 1) * 8) * 2;
                uint32_t r[4];
                ldm4(r, bHi + off);
                bhi[p*2][0] = r[0]; bhi[p*2][1] = r[1];
                bhi[p*2+1][0] = r[2]; bhi[p*2+1][1] = r[3];
                ldm4(r, bLo + off);
                blo[p*2][0] = r[0]; blo[p*2][1] = r[1];
                blo[p*2+1][0] = r[2]; blo[p*2+1][1] = r[3];
            }
#pragma unroll
            for (int mf = 0; mf < 4; mf++)
#pragma unroll
                for (int nf = 0; nf < 4; nf++) {
                    mma_bf16(acc[mf][nf], ahi[mf], bhi[nf]);
                    mma_bf16(acc[mf][nf], ahi[mf], blo[nf]);
                    mma_bf16(acc[mf][nf], alo[mf], bhi[nf]);
                }
        }
        __syncthreads();
    }

    // epilogue: C fragment -> global (guard N, optional bias)
    const int crow = lane >> 2, ccol = (lane & 3) * 2;
#pragma unroll
    for (int mf = 0; mf < 4; mf++) {
        int r0 = bm + wm + mf * 16 + crow;
#pragma unroll
        for (int nf = 0; nf < 4; nf++) {
            int c0 = bn + wn + nf * 8 + ccol;
#pragma unroll
            for (int half = 0; half < 2; half++) {
                int r = r0 + half * 8;
#pragma unroll
                for (int u = 0; u < 2; u++) {
                    int n = c0 + u;
                    if (n < Nreal) {
                        float v = acc[mf][nf][half * 2 + u];
                        if (bias) v += bias[n];
                        C[(size_t)r * ldc + n] = v;
                    }
                }
            }
        }
    }
}

// ---------------- elementwise / prep kernels ----------------
__device__ __forceinline__ void split_bf16(float x, __nv_bfloat16& h, __nv_bfloat16& l) {
    h = __float2bfloat16(x);
    l = __float2bfloat16(x - __bfloat162float(h));
}

__global__ void prep_bias_kernel(const float* __restrict__ b_ih, const float* __restrict__ b_hh) {
    int idx = blockIdx.x * 256 + threadIdx.x;
    if (idx < 4 * E) g_biassum[idx] = b_ih[idx] + b_hh[idx];
}

__global__ void conv_fc2w_kernel(const float* __restrict__ fc2_w) {
    int idx = blockIdx.x * 256 + threadIdx.x;      // NPADW*E
    int r = idx >> 8, c = idx & 255;
    float v = (r < RP1) ? fc2_w[r * E + c] : 0.f;
    split_bf16(v, g_fc2whi[idx], g_fc2wlo[idx]);
}

__global__ void conv_embT_kernel(const float* __restrict__ emb_w) {
    int k = blockIdx.x * 256 + threadIdx.x;        // grid.x = 40
    int e = blockIdx.y;                            // grid.y = 256
    float v = (k < Rr) ? emb_w[(size_t)k * E + e] : 0.f;
    split_bf16(v, g_embThi[(size_t)e * KPAD + k], g_embTlo[(size_t)e * KPAD + k]);
}

__global__ void embed_kernel(const int* __restrict__ bodys, const float* __restrict__ emb_w) {
    int idx = blockIdx.x * 256 + threadIdx.x;      // B*L*E
    int e = idx & 255, b = (idx >> 8) & 1023, t = idx >> 18;
    g_xT[idx] = emb_w[(size_t)bodys[b * L + t] * E + e];
    if (idx < Bb * E) { g_h[idx] = 0.f; g_c[idx] = 0.f; }
}

__device__ __forceinline__ float sigm(float x) { return 1.f / (1.f + __expf(-x)); }

__global__ void lstm_cell_kernel(int t) {
    int idx = blockIdx.x * 256 + threadIdx.x;      // B*E
    int b = idx >> 8, e = idx & 255;
    const float* g = g_gates + b * (4 * E);
    float gi = g[e], gf = g[E + e], gg = g[2 * E + e], go = g[3 * E + e];
    float cc = sigm(gf) * g_c[idx] + sigm(gi) * tanhf(gg);
    float hh = sigm(go) * tanhf(cc);
    g_c[idx] = cc; g_h[idx] = hh;
    g_hid[b * (L * E) + t * E + e] = hh;
}

__global__ void concat0_kernel(float* __restrict__ out_emb) {
    int idx = blockIdx.x * 256 + threadIdx.x;      // B*512
    int b = idx >> 9, j = idx & 511;
    out_emb[idx] = (j < E) ? g_xT[b * E + j] : g_xT[(1024 + b) * E + (j - E)];
}

__global__ void emb1_finish_kernel(float* __restrict__ out_emb,
                                   const float* __restrict__ emb_w, int i) {
    int idx = blockIdx.x * 256 + threadIdx.x;      // B*E
    int b = idx >> 8, e = idx & 255;
    float s = 0.f;
#pragma unroll
    for (int p = 0; p < SPLITK; p++) s += g_part[p * (Bb * E) + idx];
    s += g_psflast[b] * g_hid[b * (L * E) + i * E + e];
    out_emb[b * (2 * E) + e]     = s;
    out_emb[b * (2 * E) + E + e] = emb_w[(i + 1) * E + e];
}

__global__ void conv_h1_kernel() {
    int idx = blockIdx.x * 256 + threadIdx.x;      // B*E
    split_bf16(g_hidden1[idx], g_h1hi[idx], g_h1lo[idx]);
}

__global__ void softmax_kernel(const float* __restrict__ prob) {
    int b = blockIdx.x;
    const float* row = prob + (size_t)b * RP1;
    __nv_bfloat16* ohi = g_psfhi + (size_t)b * KPAD;
    __nv_bfloat16* olo = g_psflo + (size_t)b * KPAD;
    __shared__ float red[256];
    int t = threadIdx.x;
    float m = -1e30f;
    for (int j = t; j < RP1; j += 256) m = fmaxf(m, row[j]);
    red[t] = m; __syncthreads();
    for (int s = 128; s > 0; s >>= 1) { if (t < s) red[t] = fmaxf(red[t], red[t + s]); __syncthreads(); }
    m = red[0]; __syncthreads();
    float sum = 0.f;
    for (int j = t; j < RP1; j += 256) sum += __expf(row[j] - m);
    red[t] = sum; __syncthreads();
    for (int s = 128; s > 0; s >>= 1) { if (t < s) red[t] += red[t + s]; __syncthreads(); }
    float inv = 1.f / red[0];
    for (int j = t; j < KPAD; j += 256) {
        if (j < Rr) {
            float v = __expf(row[j] - m) * inv;
            split_bf16(v, ohi[j], olo[j]);
        } else {
            if (j == Rr) g_psflast[b] = __expf(row[j] - m) * inv;
            ohi[j] = __float2bfloat16(0.f);
            olo[j] = __float2bfloat16(0.f);
        }
    }
}

// ---------------- 128x128 FFMA2 GEMM (gx precompute) ----------------
template<bool TRANSB, bool RELU>
__global__ void __launch_bounds__(256, 2)
gemm128(const float* __restrict__ A, int lda,
        const float* __restrict__ B, int ldb,
        float* __restrict__ C, int ldc,
        int M, int N, int Klen,
        const float* __restrict__ bias)
{
    __shared__ float As[2][8][128];
    __shared__ float Bs[2][8][128];
    const int bm = blockIdx.y * 128, bn = blockIdx.x * 128;
    const int tid = threadIdx.x;
    const int tx = tid & 15, ty = tid >> 4;
    const int arow = tid >> 1, ak4 = (tid & 1) * 4;
    const int brow = tid >> 1, bk4 = (tid & 1) * 4;
    const int nkrow = tid >> 5, nn4 = (tid & 31) * 4;

    unsigned long long acc[8][4];
#pragma unroll
    for (int i = 0; i < 8; i++)
#pragma unroll
        for (int j = 0; j < 4; j++) acc[i][j] = 0ULL;

    const int ntiles = Klen >> 3;
    float4 ra, rb;
    {
        ra = *(const float4*)&A[(size_t)(bm + arow) * lda + ak4];
        if (TRANSB) rb = (bn + brow < N) ? *(const float4*)&B[(size_t)(bn + brow) * ldb + bk4]
                                         : make_float4(0.f, 0.f, 0.f, 0.f);
        else        rb = *(const float4*)&B[(size_t)nkrow * ldb + bn + nn4];
        As[0][ak4 + 0][arow] = ra.x; As[0][ak4 + 1][arow] = ra.y;
        As[0][ak4 + 2][arow] = ra.z; As[0][ak4 + 3][arow] = ra.w;
        if (TRANSB) {
            Bs[0][bk4 + 0][brow] = rb.x; Bs[0][bk4 + 1][brow] = rb.y;
            Bs[0][bk4 + 2][brow] = rb.z; Bs[0][bk4 + 3][brow] = rb.w;
        } else *(float4*)&Bs[0][nkrow][nn4] = rb;
    }
    __syncthreads();

    for (int t = 0; t < ntiles; t++) {
        const int buf = t & 1;
        if (t + 1 < ntiles) {
            const int k0 = (t + 1) * 8;
            ra = *(const float4*)&A[(size_t)(bm + arow) * lda + k0 + ak4];
            if (TRANSB) rb = (bn + brow < N) ? *(const float4*)&B[(size_t)(bn + brow) * ldb + k0 + bk4]
                                             : make_float4(0.f, 0.f, 0.f, 0.f);
            else        rb = *(const float4*)&B[(size_t)(k0 + nkrow) * ldb + bn + nn4];
            const int nb = buf ^ 1;
            As[nb][ak4 + 0][arow] = ra.x; As[nb][ak4 + 1][arow] = ra.y;
            As[nb][ak4 + 2][arow] = ra.z; As[nb][ak4 + 3][arow] = ra.w;
            if (TRANSB) {
                Bs[nb][bk4 + 0][brow] = rb.x; Bs[nb][bk4 + 1][brow] = rb.y;
                Bs[nb][bk4 + 2][brow] = rb.z; Bs[nb][bk4 + 3][brow] = rb.w;
            } else *(float4*)&Bs[nb][nkrow][nn4] = rb;
        }
#pragma unroll
        for (int kk = 0; kk < 8; kk++) {
            const float4* Ar = (const float4*)As[buf][kk];
            const float4* Br = (const float4*)Bs[buf][kk];
            float4 a0 = Ar[ty], a1 = Ar[16 + ty];
            float4 b0 = Br[tx], b1 = Br[16 + tx];
            unsigned long long bp[4];
            PACKF2(bp[0], b0.x, b0.y); PACKF2(bp[1], b0.z, b0.w);
            PACKF2(bp[2], b1.x, b1.y); PACKF2(bp[3], b1.z, b1.w);
            float av[8] = {a0.x, a0.y, a0.z, a0.w, a1.x, a1.y, a1.z, a1.w};
#pragma unroll
            for (int i = 0; i < 8; i++) {
                unsigned long long a2;
                PACKF2(a2, av[i], av[i]);
#pragma unroll
                for (int j = 0; j < 4; j++) FMAF2(acc[i][j], a2, bp[j]);
            }
        }
        __syncthreads();
    }
#pragma unroll
    for (int i = 0; i < 8; i++) {
        int m = bm + ((i < 4) ? (ty * 4 + i) : (64 + ty * 4 + i - 4));
#pragma unroll
        for (int j = 0; j < 4; j++) {
            int nbase = bn + ((j < 2) ? (tx * 4 + 2 * j) : (64 + tx * 4 + 2 * (j - 2)));
            float lo, hi;
            UNPACKF2(lo, hi, acc[i][j]);
            if (nbase < N) {
                float v = lo;
                if (bias) v += bias[nbase];
                if (RELU) v = fmaxf(v, 0.f);
                C[(size_t)m * ldc + nbase] = v;
            }
            if (nbase + 1 < N) {
                float v = hi;
                if (bias) v += bias[nbase + 1];
                if (RELU) v = fmaxf(v, 0.f);
                C[(size_t)m * ldc + nbase + 1] = v;
            }
        }
    }
}

// ---------------- 64x64 FFMA2 GEMM with optional addend (LSTM step, fc1) ----------------
#define BMT 64
#define BNT 64
#define BKT 16
template<bool TRANSB, bool RELU>
__global__ void gemm_kernel(const float* __restrict__ A, int lda,
                            const float* __restrict__ B, int ldb,
                            float* __restrict__ C, int ldc,
                            int M, int N, int Klen,
                            const float* __restrict__ bias,
                            const float* __restrict__ Cin, int ldcin)
{
    __shared__ float As[BKT][BMT + 4];
    __shared__ float Bs[BKT][BNT + 4];
    int bm = blockIdx.y * BMT, bn = blockIdx.x * BNT;
    int tid = threadIdx.x;
    int tx = tid & 15, ty = tid >> 4;
    unsigned long long acc[4][2];
#pragma unroll
    for (int i = 0; i < 4; i++) { acc[i][0] = 0ULL; acc[i][1] = 0ULL; }

    for (int kt = 0; kt < Klen; kt += BKT) {
#pragma unroll
        for (int j = 0; j < 4; j++) {
            int idx = tid + j * 256;
            int m = idx >> 4, k = idx & 15;
            As[k][m] = A[(size_t)(bm + m) * lda + kt + k];
        }
#pragma unroll
        for (int j = 0; j < 4; j++) {
            int idx = tid + j * 256;
            if (TRANSB) {
                int n = idx >> 4, k = idx & 15;
                Bs[k][n] = (bn + n < N) ? B[(size_t)(bn + n) * ldb + kt + k] : 0.f;
            } else {
                int k = idx >> 6, n = idx & 63;
                Bs[k][n] = (bn + n < N) ? B[(size_t)(kt + k) * ldb + bn + n] : 0.f;
            }
        }
        __syncthreads();
#pragma unroll
        for (int kk = 0; kk < BKT; kk++) {
            float4 a4 = *(const float4*)&As[kk][ty * 4];
            float4 b4 = *(const float4*)&Bs[kk][tx * 4];
            unsigned long long bp0, bp1;
            PACKF2(bp0, b4.x, b4.y); PACKF2(bp1, b4.z, b4.w);
            float av[4] = {a4.x, a4.y, a4.z, a4.w};
#pragma unroll
            for (int i = 0; i < 4; i++) {
                unsigned long long a2;
                PACKF2(a2, av[i], av[i]);
                FMAF2(acc[i][0], a2, bp0);
                FMAF2(acc[i][1], a2, bp1);
            }
        }
        __syncthreads();
    }
#pragma unroll
    for (int i = 0; i < 4; i++) {
        int m = bm + ty * 4 + i;
#pragma unroll
        for (int j = 0; j < 2; j++) {
            int nbase = bn + tx * 4 + 2 * j;
            float lo, hi;
            UNPACKF2(lo, hi, acc[i][j]);
#pragma unroll
            for (int u = 0; u < 2; u++) {
                int n = nbase + u;
                if (n < N) {
                    float v = (u == 0) ? lo : hi;
                    if (Cin) v += Cin[(size_t)m * ldcin + n];
                    else if (bias) v += bias[n];
                    if (RELU) v = fmaxf(v, 0.f);
                    C[(size_t)m * ldc + n] = v;
                }
            }
        }
    }
}

// ---------------- launch ----------------
extern "C" void kernel_launch(void* const* d_in, const int* in_sizes, int n_in,
                              void* d_out, int out_size) {
    const int*   bodys = (const int*)  d_in[0];
    const float* emb_w = (const float*)d_in[1];
    const float* w_ih  = (const float*)d_in[2];
    const float* w_hh  = (const float*)d_in[3];
    const float* b_ih  = (const float*)d_in[4];
    const float* b_hh  = (const float*)d_in[5];
    const float* fc1_w = (const float*)d_in[6];
    const float* fc1_b = (const float*)d_in[7];
    const float* fc2_w = (const float*)d_in[8];
    const float* fc2_b = (const float*)d_in[9];

    float* out_prob = (float*)d_out;
    float* out_emb  = out_prob + (size_t)Bb * RP1;

    float *hidden1, *biassum, *part, *gx, *h, *gates, *xT;
    __nv_bfloat16 *h1hi, *h1lo, *psfhi, *psflo, *eThi, *eTlo, *f2hi, *f2lo;
    cudaGetSymbolAddress((void**)&hidden1, g_hidden1);
    cudaGetSymbolAddress((void**)&biassum, g_biassum);
    cudaGetSymbolAddress((void**)&part,    g_part);
    cudaGetSymbolAddress((void**)&gx,      g_gx);
    cudaGetSymbolAddress((void**)&h,       g_h);
    cudaGetSymbolAddress((void**)&gates,   g_gates);
    cudaGetSymbolAddress((void**)&xT,      g_xT);
    cudaGetSymbolAddress((void**)&h1hi,    g_h1hi);
    cudaGetSymbolAddress((void**)&h1lo,    g_h1lo);
    cudaGetSymbolAddress((void**)&psfhi,   g_psfhi);
    cudaGetSymbolAddress((void**)&psflo,   g_psflo);
    cudaGetSymbolAddress((void**)&eThi,    g_embThi);
    cudaGetSymbolAddress((void**)&eTlo,    g_embTlo);
    cudaGetSymbolAddress((void**)&f2hi,    g_fc2whi);
    cudaGetSymbolAddress((void**)&f2lo,    g_fc2wlo);

    prep_bias_kernel<<<4, 256>>>(b_ih, b_hh);
    conv_fc2w_kernel<<<(NPADW * E) / 256, 256>>>(fc2_w);
    conv_embT_kernel<<<dim3(40, 256), 256>>>(emb_w);
    embed_kernel<<<8192, 256>>>(bodys, emb_w);

    // gx[t*1024+b] = x_t @ w_ih^T + (b_ih + b_hh)
    gemm128<true, false><<<dim3(8, 64), 256>>>(
        xT, E, w_ih, E, gx, 4 * E, Bb * L, 4 * E, E, biassum);

    // LSTM steps: gates = h @ w_hh^T + gx_t
    for (int t = 0; t < L; t++) {
        gemm_kernel<true, false><<<dim3(16, 16), 256>>>(
            h, E, w_hh, E, gates, 4 * E, Bb, 4 * E, E,
            nullptr, gx + (size_t)t * Bb * 4 * E, 4 * E);
        lstm_cell_kernel<<<1024, 256>>>(t);
    }

    for (int i = 0; i < L - 1; i++) {
        if (i == 0) {
            concat0_kernel<<<2048, 256>>>(out_emb);
        } else {
            // emb_1 = prob_sf[:, :R] @ emb_w : warp-MMA split-bf16, split-K x10
            hmma_gemm<<<dim3(2, 8, SPLITK), 256>>>(
                psfhi, psflo, KPAD, eThi, eTlo, KPAD,
                part, E, E, KSPL, (size_t)Bb * E, nullptr);
            emb1_finish_kernel<<<1024, 256>>>(out_emb, emb_w, i);
        }
        // hidden1 = relu(emb_concat @ fc1_w^T + fc1_b)
        gemm_kernel<true, true><<<dim3(4, 16), 256>>>(
            out_emb, 2 * E, fc1_w, 2 * E, hidden1, E, Bb, E, 2 * E,
            fc1_b, nullptr, 0);
        conv_h1_kernel<<<1024, 256>>>();
        // prob = hidden1 @ fc2_w^T + fc2_b : warp-MMA split-bf16
        hmma_gemm<<<dim3(79, 8, 1), 256>>>(
            h1hi, h1lo, E, f2hi, f2lo, E,
            out_prob, RP1, RP1, E, 0, fc2_b);
        if (i < L - 2) softmax_kernel<<<1024, 256>>>(out_prob);
    }
}